// round 4
// baseline (speedup 1.0000x reference)
#include <cuda_runtime.h>
#include <cuda_bf16.h>
#include <math.h>
#include <stdint.h>

// ---------------- constants ----------------
#define DIMC   384
#define HEADS  8
#define HD     48            // head dim
#define NADLA  343           // 7^3 anchors
#define HWD    14
#define NTOK   2744          // 14^3
#define BATCH  8
#define MTOT   (BATCH*NTOK)  // 21952
#define SCALE  0.14433756729740643f  // 48^-0.5

// ---------------- device scratch ----------------
__device__ float g_q   [(long long)MTOT*DIMC];           // 33.7 MB
__device__ float g_kv  [(long long)MTOT*2*DIMC];         // 67.5 MB
__device__ float g_adla[(long long)BATCH*NADLA*DIMC];    // 4.2 MB
__device__ float g_pb  [(long long)HEADS*NADLA*NTOK];    // 30.1 MB
__device__ float g_ab  [(long long)HEADS*NTOK*NADLA];    // 30.1 MB
__device__ float g_logits[(long long)BATCH*HEADS*NADLA*NTOK]; // 241 MB (reused)
__device__ float g_adlav[(long long)BATCH*HEADS*NADLA*HD];    // 4.2 MB
__device__ float g_attn[(long long)MTOT*DIMC];           // 33.7 MB

static inline int cdiv(int a, int b) { return (a + b - 1) / b; }

// ---------------- tf32 helpers ----------------
__device__ __forceinline__ float tf32_rna(float f)
{
    uint32_t r;
    asm("cvt.rna.tf32.f32 %0, %1;" : "=r"(r) : "f"(f));
    return __uint_as_float(r);
}

__device__ __forceinline__ void mma_tf32(float c[4], uint32_t a0, uint32_t a1,
                                         uint32_t a2, uint32_t a3,
                                         uint32_t b0, uint32_t b1)
{
    asm volatile(
        "mma.sync.aligned.m16n8k8.row.col.f32.tf32.tf32.f32 "
        "{%0,%1,%2,%3}, {%4,%5,%6,%7}, {%8,%9}, {%0,%1,%2,%3};"
        : "+f"(c[0]), "+f"(c[1]), "+f"(c[2]), "+f"(c[3])
        : "r"(a0), "r"(a1), "r"(a2), "r"(a3), "r"(b0), "r"(b1));
}

// ---------------- 3xTF32 tensor-core GEMM ----------------
// C[M,N] = alpha * A @ op(B) + bias[col] + Add[row,col]
// BT=false: B row-major [K,N].  BT=true: B row-major [N,K] (i.e. A@B^T).
// Batched over gridDim.z: z -> (b = z>>3, h = z&7) strides.
// Tile: 128x128x16, 256 threads, 8 warps of 64x32.
// Shared layout: hi/lo interleaved pairs, row stride 264 words (conflict-free
// LDS.64 fragment loads: 264 mod 32 == 8).
#define BM 128
#define BN 128
#define ROW 264

template<bool BT>
__global__ void __launch_bounds__(256)
mma_gemm(const float* __restrict__ A, const float* __restrict__ B,
         float* __restrict__ C, const float* __restrict__ bias,
         const float* __restrict__ Add,
         int M, int N, int K, int lda, int ldb, int ldc, int ldadd,
         long long sAb, long long sAh, long long sBb, long long sBh,
         long long sCb, long long sCh, long long sAddh, float alpha)
{
    __shared__ float As[16][ROW];
    __shared__ float Bs[16][ROW];

    int bz = blockIdx.z;
    int bb = bz >> 3, hh = bz & 7;
    A += bb * sAb + hh * sAh;
    B += bb * sBb + hh * sBh;
    C += bb * sCb + hh * sCh;
    if (Add) Add += (long long)hh * sAddh;

    const int tid = threadIdx.x;
    const int warp = tid >> 5, lane = tid & 31;
    const int wm = warp & 1, wn = warp >> 1;          // 2 x 4 warp grid
    const int gid = lane >> 2, ctg = lane & 3;        // mma thread layout
    const int row0 = blockIdx.y * BM, col0 = blockIdx.x * BN;

    const bool alA = (lda & 3) == 0;
    const bool alB = (ldb & 3) == 0;

    float acc[4][4][4];
#pragma unroll
    for (int i = 0; i < 4; i++)
#pragma unroll
        for (int j = 0; j < 4; j++)
#pragma unroll
            for (int t = 0; t < 4; t++) acc[i][j][t] = 0.f;

    for (int k0 = 0; k0 < K; k0 += 16) {
        // ---- stage A: [BM rows] x [16 k], hi/lo pairs, transposed to As[k][2m] ----
#pragma unroll
        for (int i = 0; i < 2; i++) {
            int f = tid + i * 256;
            int r = f >> 2;
            int kq = (f & 3) << 2;
            int gr = row0 + r;
            float v[4] = {0.f, 0.f, 0.f, 0.f};
            if (gr < M) {
                int gk = k0 + kq;
                if (alA && gk + 3 < K) {
                    float4 t = *(const float4*)(A + (long long)gr * lda + gk);
                    v[0] = t.x; v[1] = t.y; v[2] = t.z; v[3] = t.w;
                } else {
#pragma unroll
                    for (int j = 0; j < 4; j++)
                        if (gk + j < K) v[j] = A[(long long)gr * lda + gk + j];
                }
            }
#pragma unroll
            for (int j = 0; j < 4; j++) {
                float hi = tf32_rna(v[j]);
                float lo = tf32_rna(v[j] - hi);
                As[kq + j][2 * r]     = hi;
                As[kq + j][2 * r + 1] = lo;
            }
        }
        // ---- stage B ----
        if (!BT) {
            // B row-major [K,N]: Bs[k][2n] pairs
#pragma unroll
            for (int i = 0; i < 2; i++) {
                int f = tid + i * 256;
                int kk = f >> 5;
                int nq = (f & 31) << 2;
                int gk = k0 + kk;
                float v[4] = {0.f, 0.f, 0.f, 0.f};
                if (gk < K) {
                    int gc = col0 + nq;
                    if (alB && gc + 3 < N) {
                        float4 t = *(const float4*)(B + (long long)gk * ldb + gc);
                        v[0] = t.x; v[1] = t.y; v[2] = t.z; v[3] = t.w;
                    } else {
#pragma unroll
                        for (int j = 0; j < 4; j++)
                            if (gc + j < N) v[j] = B[(long long)gk * ldb + gc + j];
                    }
                }
#pragma unroll
                for (int j = 0; j < 4; j++) {
                    float hi = tf32_rna(v[j]);
                    float lo = tf32_rna(v[j] - hi);
                    Bs[kk][2 * (nq + j)]     = hi;
                    Bs[kk][2 * (nq + j) + 1] = lo;
                }
            }
        } else {
            // B row-major [N,K]: transpose like A
#pragma unroll
            for (int i = 0; i < 2; i++) {
                int f = tid + i * 256;
                int r = f >> 2;
                int kq = (f & 3) << 2;
                int gc = col0 + r;
                float v[4] = {0.f, 0.f, 0.f, 0.f};
                if (gc < N) {
                    int gk = k0 + kq;
                    if (alB && gk + 3 < K) {
                        float4 t = *(const float4*)(B + (long long)gc * ldb + gk);
                        v[0] = t.x; v[1] = t.y; v[2] = t.z; v[3] = t.w;
                    } else {
#pragma unroll
                        for (int j = 0; j < 4; j++)
                            if (gk + j < K) v[j] = B[(long long)gc * ldb + gk + j];
                    }
                }
#pragma unroll
                for (int j = 0; j < 4; j++) {
                    float hi = tf32_rna(v[j]);
                    float lo = tf32_rna(v[j] - hi);
                    Bs[kq + j][2 * r]     = hi;
                    Bs[kq + j][2 * r + 1] = lo;
                }
            }
        }
        __syncthreads();

        // ---- compute: 2 k8 steps ----
#pragma unroll
        for (int k8 = 0; k8 < 2; k8++) {
            int kb = k8 * 8;
            uint32_t Ah[4][4], Al[4][4], Bh[4][2], Bl[4][2];
#pragma unroll
            for (int mt = 0; mt < 4; mt++) {
                int m = wm * 64 + mt * 16 + gid;
                float2 p0 = *(const float2*)&As[kb + ctg][2 * m];
                float2 p1 = *(const float2*)&As[kb + ctg][2 * (m + 8)];
                float2 p2 = *(const float2*)&As[kb + ctg + 4][2 * m];
                float2 p3 = *(const float2*)&As[kb + ctg + 4][2 * (m + 8)];
                Ah[mt][0] = __float_as_uint(p0.x); Al[mt][0] = __float_as_uint(p0.y);
                Ah[mt][1] = __float_as_uint(p1.x); Al[mt][1] = __float_as_uint(p1.y);
                Ah[mt][2] = __float_as_uint(p2.x); Al[mt][2] = __float_as_uint(p2.y);
                Ah[mt][3] = __float_as_uint(p3.x); Al[mt][3] = __float_as_uint(p3.y);
            }
#pragma unroll
            for (int nt = 0; nt < 4; nt++) {
                int n = wn * 32 + nt * 8 + gid;
                float2 q0 = *(const float2*)&Bs[kb + ctg][2 * n];
                float2 q1 = *(const float2*)&Bs[kb + ctg + 4][2 * n];
                Bh[nt][0] = __float_as_uint(q0.x); Bl[nt][0] = __float_as_uint(q0.y);
                Bh[nt][1] = __float_as_uint(q1.x); Bl[nt][1] = __float_as_uint(q1.y);
            }
#pragma unroll
            for (int mt = 0; mt < 4; mt++)
#pragma unroll
                for (int nt = 0; nt < 4; nt++) {
                    // 3xTF32: hi*hi + hi*lo + lo*hi
                    mma_tf32(acc[mt][nt], Ah[mt][0], Ah[mt][1], Ah[mt][2], Ah[mt][3],
                             Bh[nt][0], Bh[nt][1]);
                    mma_tf32(acc[mt][nt], Ah[mt][0], Ah[mt][1], Ah[mt][2], Ah[mt][3],
                             Bl[nt][0], Bl[nt][1]);
                    mma_tf32(acc[mt][nt], Al[mt][0], Al[mt][1], Al[mt][2], Al[mt][3],
                             Bh[nt][0], Bh[nt][1]);
                }
        }
        __syncthreads();
    }

    // ---- epilogue ----
#pragma unroll
    for (int mt = 0; mt < 4; mt++) {
#pragma unroll
        for (int nt = 0; nt < 4; nt++) {
#pragma unroll
            for (int t = 0; t < 4; t++) {
                int gr = row0 + wm * 64 + mt * 16 + gid + ((t >> 1) ? 8 : 0);
                int gc = col0 + wn * 32 + nt * 8 + 2 * ctg + (t & 1);
                if (gr < M && gc < N) {
                    float v = alpha * acc[mt][nt][t];
                    if (bias) v += bias[gc];
                    if (Add)  v += Add[(long long)gr * ldadd + gc];
                    C[(long long)gr * ldc + gc] = v;
                }
            }
        }
    }
}

// ---------------- pooling: adla[b,a,c] = mean of 2x2x2 block of q ----------------
__global__ void pool_adla(const float* __restrict__ q, float* __restrict__ adla)
{
    int idx = blockIdx.x * 256 + threadIdx.x;
    if (idx >= BATCH * NADLA * DIMC) return;
    int c = idx % DIMC;
    int a = (idx / DIMC) % NADLA;
    int b = idx / (DIMC * NADLA);
    int a1 = a / 49, a2 = (a / 7) % 7, a3 = a % 7;
    float s = 0.f;
#pragma unroll
    for (int i = 0; i < 2; i++)
#pragma unroll
        for (int j = 0; j < 2; j++)
#pragma unroll
            for (int k = 0; k < 2; k++) {
                int n = ((2 * a1 + i) * HWD + (2 * a2 + j)) * HWD + (2 * a3 + k);
                s += q[((long long)(b * NTOK + n)) * DIMC + c];
            }
    adla[idx] = s * 0.125f;
}

// linear-interp helper: out index o (0..13) from 7 inputs
__device__ __forceinline__ void lin_w(int o, int& i0, int& i1, float& w)
{
    float x = 0.5f * o - 0.25f;
    x = fminf(fmaxf(x, 0.f), 6.f);
    i0 = (int)floorf(x);
    i1 = min(i0 + 1, 6);
    w = x - (float)i0;
}

__device__ __forceinline__ float interp3(const float* base, int x, int y, int z)
{
    int x0, x1, y0, y1, z0, z1;
    float wx, wy, wz;
    lin_w(x, x0, x1, wx);
    lin_w(y, y0, y1, wy);
    lin_w(z, z0, z1, wz);
    float c000 = base[x0 * 49 + y0 * 7 + z0], c001 = base[x0 * 49 + y0 * 7 + z1];
    float c010 = base[x0 * 49 + y1 * 7 + z0], c011 = base[x0 * 49 + y1 * 7 + z1];
    float c100 = base[x1 * 49 + y0 * 7 + z0], c101 = base[x1 * 49 + y0 * 7 + z1];
    float c110 = base[x1 * 49 + y1 * 7 + z0], c111 = base[x1 * 49 + y1 * 7 + z1];
    float v0 = (1.f - wy) * ((1.f - wz) * c000 + wz * c001) + wy * ((1.f - wz) * c010 + wz * c011);
    float v1 = (1.f - wy) * ((1.f - wz) * c100 + wz * c101) + wy * ((1.f - wz) * c110 + wz * c111);
    return (1.f - wx) * v0 + wx * v1;
}

// pb[h,a,n] = interp(an_bias)[h,a,n] + ah[h,a,x] + aw[h,a,y] + ad[h,a,z]
__global__ void pb_kernel(const float* __restrict__ an, const float* __restrict__ ah,
                          const float* __restrict__ aw, const float* __restrict__ ad,
                          float* __restrict__ pb)
{
    int idx = blockIdx.x * 256 + threadIdx.x;
    if (idx >= HEADS * NADLA * NTOK) return;
    int n = idx % NTOK;
    int a = (idx / NTOK) % NADLA;
    int h = idx / (NTOK * NADLA);
    int x = n / 196, y = (n / 14) % 14, z = n % 14;
    const float* base = an + ((long long)(h * NADLA + a)) * NADLA;
    float v = interp3(base, x, y, z);
    v += ah[(h * NADLA + a) * HWD + x];
    v += aw[(h * NADLA + a) * HWD + y];
    v += ad[(h * NADLA + a) * HWD + z];
    pb[idx] = v;
}

// ab[h,n,a] = interp(na_bias)[h,a,n] + ha[h,x,a] + wa[h,y,a] + da[h,z,a]
__global__ void ab_kernel(const float* __restrict__ na, const float* __restrict__ ha,
                          const float* __restrict__ wa, const float* __restrict__ da,
                          float* __restrict__ ab)
{
    int idx = blockIdx.x * 256 + threadIdx.x;
    if (idx >= HEADS * NTOK * NADLA) return;
    int a = idx % NADLA;
    int n = (idx / NADLA) % NTOK;
    int h = idx / (NADLA * NTOK);
    int x = n / 196, y = (n / 14) % 14, z = n % 14;
    const float* base = na + ((long long)(h * NADLA + a)) * NADLA;
    float v = interp3(base, x, y, z);
    v += ha[(h * HWD + x) * NADLA + a];
    v += wa[(h * HWD + y) * NADLA + a];
    v += da[(h * HWD + z) * NADLA + a];
    ab[idx] = v;
}

// ---------------- softmax over rows ----------------
__device__ __forceinline__ float warpRedMax(float v)
{
#pragma unroll
    for (int o = 16; o; o >>= 1) v = fmaxf(v, __shfl_xor_sync(0xffffffffu, v, o));
    return v;
}
__device__ __forceinline__ float warpRedSum(float v)
{
#pragma unroll
    for (int o = 16; o; o >>= 1) v += __shfl_xor_sync(0xffffffffu, v, o);
    return v;
}

__global__ void softmax_rows(float* __restrict__ data, int len)
{
    extern __shared__ float s[];
    float* red = s + len;
    float* row = data + (long long)blockIdx.x * len;
    int tid = threadIdx.x, nth = blockDim.x;
    int lane = tid & 31, w = tid >> 5, nw = nth >> 5;

    float m = -3.4e38f;
    for (int i = tid; i < len; i += nth) {
        float v = row[i];
        s[i] = v;
        m = fmaxf(m, v);
    }
    m = warpRedMax(m);
    if (lane == 0) red[w] = m;
    __syncthreads();
    m = (lane < nw) ? red[lane] : -3.4e38f;
    m = warpRedMax(m);
    m = __shfl_sync(0xffffffffu, m, 0);
    __syncthreads();

    float sum = 0.f;
    for (int i = tid; i < len; i += nth) {
        float e = __expf(s[i] - m);
        s[i] = e;
        sum += e;
    }
    sum = warpRedSum(sum);
    if (lane == 0) red[w] = sum;
    __syncthreads();
    sum = (lane < nw) ? red[lane] : 0.f;
    sum = warpRedSum(sum);
    sum = __shfl_sync(0xffffffffu, sum, 0);
    float inv = 1.f / sum;
    for (int i = tid; i < len; i += nth) row[i] = s[i] * inv;
}

// ---------------- depthwise 3x3x3 conv on v, added into attn buffer ----------------
__global__ void dwc_add(const float* __restrict__ kv, const float* __restrict__ w,
                        const float* __restrict__ bias, float* __restrict__ attn)
{
    int blk = blockIdx.x; // b*NTOK + n
    int c = threadIdx.x;  // 0..383
    int b = blk / NTOK, n = blk % NTOK;
    int x = n / 196, y = (n / 14) % 14, z = n % 14;
    float acc = bias[c];
    const float* wc = w + c * 27;
#pragma unroll
    for (int i = -1; i <= 1; i++) {
        int xx = x + i;
        if ((unsigned)xx >= (unsigned)HWD) continue;
#pragma unroll
        for (int j = -1; j <= 1; j++) {
            int yy = y + j;
            if ((unsigned)yy >= (unsigned)HWD) continue;
#pragma unroll
            for (int k = -1; k <= 1; k++) {
                int zz = z + k;
                if ((unsigned)zz >= (unsigned)HWD) continue;
                int nn = (xx * HWD + yy) * HWD + zz;
                acc = fmaf(kv[((long long)(b * NTOK + nn)) * 768 + DIMC + c],
                           wc[(i + 1) * 9 + (j + 1) * 3 + (k + 1)], acc);
            }
        }
    }
    attn[(long long)blk * DIMC + c] += acc;
}

// ---------------- launcher ----------------
extern "C" void kernel_launch(void* const* d_in, const int* in_sizes, int n_in,
                              void* d_out, int out_size)
{
    const float* x     = (const float*)d_in[0];
    const float* Wq    = (const float*)d_in[1];
    const float* Wkv   = (const float*)d_in[2];
    const float* Wproj = (const float*)d_in[3];
    const float* bproj = (const float*)d_in[4];
    const float* dwcw  = (const float*)d_in[5];
    const float* dwcb  = (const float*)d_in[6];
    const float* an    = (const float*)d_in[7];
    const float* na    = (const float*)d_in[8];
    const float* ah    = (const float*)d_in[9];
    const float* aw    = (const float*)d_in[10];
    const float* ad    = (const float*)d_in[11];
    const float* ha    = (const float*)d_in[12];
    const float* wa    = (const float*)d_in[13];
    const float* da    = (const float*)d_in[14];
    float* out = (float*)d_out;

    void* p;
    cudaGetSymbolAddress(&p, g_q);      float* q    = (float*)p;
    cudaGetSymbolAddress(&p, g_kv);     float* kv   = (float*)p;
    cudaGetSymbolAddress(&p, g_adla);   float* adla = (float*)p;
    cudaGetSymbolAddress(&p, g_pb);     float* pb   = (float*)p;
    cudaGetSymbolAddress(&p, g_ab);     float* ab   = (float*)p;
    cudaGetSymbolAddress(&p, g_logits); float* lg   = (float*)p;
    cudaGetSymbolAddress(&p, g_adlav);  float* av   = (float*)p;
    cudaGetSymbolAddress(&p, g_attn);   float* at   = (float*)p;

    // 1) q = x @ Wq   (M=21952, N=384, K=384), NN
    mma_gemm<false><<<dim3(cdiv(DIMC, BN), cdiv(MTOT, BM), 1), 256>>>(
        x, Wq, q, nullptr, nullptr,
        MTOT, DIMC, DIMC, DIMC, DIMC, DIMC, 0,
        0, 0, 0, 0, 0, 0, 0, 1.0f);
    // 2) kv = x @ Wkv (N=768), NN
    mma_gemm<false><<<dim3(cdiv(768, BN), cdiv(MTOT, BM), 1), 256>>>(
        x, Wkv, kv, nullptr, nullptr,
        MTOT, 768, DIMC, DIMC, 768, 768, 0,
        0, 0, 0, 0, 0, 0, 0, 1.0f);
    // 3) pooled anchors
    pool_adla<<<cdiv(BATCH * NADLA * DIMC, 256), 256>>>(q, adla);
    // 4) positional bias tables
    pb_kernel<<<cdiv(HEADS * NADLA * NTOK, 256), 256>>>(an, ah, aw, ad, pb);
    ab_kernel<<<cdiv(HEADS * NTOK * NADLA, 256), 256>>>(na, ha, wa, da, ab);

    // 5) logits1[bh, a, n] = SCALE * adla_h @ k_h^T + pb[h]   (NT, M=343, N=2744, K=48)
    mma_gemm<true><<<dim3(cdiv(NTOK, BN), cdiv(NADLA, BM), BATCH * HEADS), 256>>>(
        adla, kv, lg, nullptr, pb,
        NADLA, NTOK, HD, DIMC, 768, NTOK, NTOK,
        (long long)NADLA * DIMC, HD,
        (long long)NTOK * 768, HD,
        (long long)HEADS * NADLA * NTOK, (long long)NADLA * NTOK,
        (long long)NADLA * NTOK, SCALE);
    // 6) softmax over n
    softmax_rows<<<BATCH * HEADS * NADLA, 256, (NTOK + 32) * sizeof(float)>>>(lg, NTOK);
    // 7) adla_v[bh, a, d] = P1 @ v_h   (NN, M=343, N=48, K=2744)
    mma_gemm<false><<<dim3(1, cdiv(NADLA, BM), BATCH * HEADS), 256>>>(
        lg, kv + DIMC, av, nullptr, nullptr,
        NADLA, HD, NTOK, NTOK, 768, HD, 0,
        (long long)HEADS * NADLA * NTOK, (long long)NADLA * NTOK,
        (long long)NTOK * 768, HD,
        (long long)HEADS * NADLA * HD, (long long)NADLA * HD, 0, 1.0f);

    // 8) logits2[bh, n, a] = SCALE * q_h @ adla_h^T + ab[h]   (NT, M=2744, N=343, K=48)
    mma_gemm<true><<<dim3(cdiv(NADLA, BN), cdiv(NTOK, BM), BATCH * HEADS), 256>>>(
        q, adla, lg, nullptr, ab,
        NTOK, NADLA, HD, DIMC, DIMC, NADLA, NADLA,
        (long long)NTOK * DIMC, HD,
        (long long)NADLA * DIMC, HD,
        (long long)HEADS * NTOK * NADLA, (long long)NTOK * NADLA,
        (long long)NTOK * NADLA, SCALE);
    // 9) softmax over a
    softmax_rows<<<BATCH * HEADS * NTOK, 128, (NADLA + 32) * sizeof(float)>>>(lg, NADLA);
    // 10) attn[b, n, h*48+d] = P2 @ adla_v  (NN, M=2744, N=48, K=343; lda=343 -> scalar path)
    mma_gemm<false><<<dim3(1, cdiv(NTOK, BM), BATCH * HEADS), 256>>>(
        lg, av, at, nullptr, nullptr,
        NTOK, HD, NADLA, NADLA, HD, DIMC, 0,
        (long long)HEADS * NTOK * NADLA, (long long)NTOK * NADLA,
        (long long)HEADS * NADLA * HD, (long long)NADLA * HD,
        (long long)NTOK * DIMC, HD, 0, 1.0f);

    // 11) depthwise conv on v, accumulate into attn
    dwc_add<<<BATCH * NTOK, DIMC>>>(kv, dwcw, dwcb, at);

    // 12) out = attn @ Wproj + bproj  (NN)
    mma_gemm<false><<<dim3(cdiv(DIMC, BN), cdiv(MTOT, BM), 1), 256>>>(
        at, Wproj, out, bproj, nullptr,
        MTOT, DIMC, DIMC, DIMC, DIMC, DIMC, 0,
        0, 0, 0, 0, 0, 0, 0, 1.0f);
}